// round 15
// baseline (speedup 1.0000x reference)
#include <cuda_runtime.h>
#include <cuda_bf16.h>
#include <cstdint>
#include <math.h>

// ---------------------------------------------------------------------------
// Problem: D=1024, H=16 (hd=64), DFF=4096, S=5, B=2048, L=6.
// tokens = 6*2048*6 = 73728 ; queries = 20480 ; U rows = 12288
// ---------------------------------------------------------------------------

// ----------------- scratch (device globals; allocation is banned) ----------
__device__ __align__(128) float g_src [75497472];   // [73728,1024] src tokens (verb | noun+role)
__device__ __align__(128) float g_qsrc[20971520];   // [20480,1024] gathered query tokens
__device__ __align__(128) float g_kv  [150994944];  // [73728,2048] K|V
__device__ __align__(128) float g_q   [20971520];   // [20480,1024] Q
__device__ __align__(128) float g_o   [20971520];   // attention out
__device__ __align__(128) float g_m   [20971520];   // messages (after out-proj)
__device__ __align__(128) float g_hid [50331648];   // [12288,4096] ffn hidden
__device__ __align__(128) float g_u   [12582912];   // [12288,1024] post-LN residual input
__device__ __align__(128) float g_ffn [12582912];   // [12288,1024] ffn out
__device__ __align__(128) float g_aggA[2097152];    // sigmoid(verb msgs @ agg1) -> added to nouns
__device__ __align__(128) float g_aggB[2097152];    // sigmoid(noun msgs @ agg2) -> added to verb

// ----------------- build src tokens + gather queries ------------------------
__global__ __launch_bounds__(256) void build_src_kernel(
    const float* __restrict__ feat, const float* __restrict__ role,
    float* __restrict__ src, float* __restrict__ qsrc)
{
    int token = blockIdx.x;                 // ((s*2048+b)*6 + t)
    int t  = token % 6;
    int sb = token / 6;
    int s  = sb >> 11, b = sb & 2047;
    int c  = threadIdx.x * 4;
    float4 v = *reinterpret_cast<const float4*>(feat + (size_t)token * 1024 + c);
    if (t > 0) {
        float4 r = *reinterpret_cast<const float4*>(role + ((size_t)sb * 5 + (t - 1)) * 1024 + c);
        v.x += r.x; v.y += r.y; v.z += r.z; v.w += r.w;
    }
    *reinterpret_cast<float4*>(src + (size_t)token * 1024 + c) = v;
    int qrow = -1;
    if (s == 0 && t > 0)      qrow = b * 5 + (t - 1);          // noun queries (scene 0)
    else if (t == 0 && s > 0) qrow = 10240 + b * 5 + (s - 1);  // verb queries (scenes 1..5)
    if (qrow >= 0)
        *reinterpret_cast<float4*>(qsrc + (size_t)qrow * 1024 + c) = v;
}

// ----------------- generic tf32 GEMM: C = act(A[M,K] @ B[N,K]^T + bias) -----
#define SST 36   // smem row stride (32 + 4 pad) in floats

#define LOAD_TILE(buf, k0)                                                                 \
    {                                                                                      \
        _Pragma("unroll")                                                                  \
        for (int i_ = 0; i_ < 4; i_++) {                                                   \
            int ch = i_ * 256 + tid;                                                       \
            int row = ch >> 3, c4 = ch & 7;                                                \
            const float* pa = Ag + (size_t)(bm + row) * K + (k0) + c4 * 4;                 \
            uint32_t da = sAu + (uint32_t)(((((buf) * 128 + row) * SST) + c4 * 4) * 4);    \
            asm volatile("cp.async.cg.shared.global [%0], [%1], 16;\n" :: "r"(da), "l"(pa)); \
            const float* pb = Bg + (size_t)(bn + row) * K + (k0) + c4 * 4;                 \
            uint32_t db = sBu + (uint32_t)(((((buf) * 128 + row) * SST) + c4 * 4) * 4);    \
            asm volatile("cp.async.cg.shared.global [%0], [%1], 16;\n" :: "r"(db), "l"(pb)); \
        }                                                                                  \
        asm volatile("cp.async.commit_group;\n");                                          \
    }

template <int ACT>  // 0 none, 1 relu, 2 sigmoid
__global__ __launch_bounds__(256) void gemm_tf32(
    const float* __restrict__ Ag, const float* __restrict__ Bg,
    const float* __restrict__ bias, float* __restrict__ C,
    int M, int N, int K)
{
    extern __shared__ float sm[];
    float* sA = sm;                    // [2][128][SST]
    float* sB = sm + 2 * 128 * SST;
    const int tid  = threadIdx.x;
    const int lane = tid & 31, warp = tid >> 5;
    const int wm = warp & 1, wn = warp >> 1;      // 2(M) x 4(N) warps, 64x32 per warp
    const int bm = blockIdx.y * 128, bn = blockIdx.x * 128;
    uint32_t sAu = (uint32_t)__cvta_generic_to_shared(sA);
    uint32_t sBu = (uint32_t)__cvta_generic_to_shared(sB);

    float acc[4][4][4] = {};
    const int KT = K >> 5;

    LOAD_TILE(0, 0);

    for (int kt = 0; kt < KT; kt++) {
        int buf = kt & 1;
        if (kt + 1 < KT) {
            LOAD_TILE(buf ^ 1, (kt + 1) * 32);
            asm volatile("cp.async.wait_group 1;\n");
        } else {
            asm volatile("cp.async.wait_group 0;\n");
        }
        __syncthreads();
        const float* At = sA + buf * 128 * SST;
        const float* Bt = sB + buf * 128 * SST;
#pragma unroll
        for (int ks = 0; ks < 4; ks++) {
            const int kc = ks * 8 + (lane & 3);
            const int ar = wm * 64 + (lane >> 2);
            uint32_t a[4][4];
#pragma unroll
            for (int mi = 0; mi < 4; mi++) {
                float f0 = At[(ar + mi * 16)     * SST + kc];
                float f1 = At[(ar + mi * 16 + 8) * SST + kc];
                float f2 = At[(ar + mi * 16)     * SST + kc + 4];
                float f3 = At[(ar + mi * 16 + 8) * SST + kc + 4];
                asm("cvt.rna.tf32.f32 %0, %1;" : "=r"(a[mi][0]) : "f"(f0));
                asm("cvt.rna.tf32.f32 %0, %1;" : "=r"(a[mi][1]) : "f"(f1));
                asm("cvt.rna.tf32.f32 %0, %1;" : "=r"(a[mi][2]) : "f"(f2));
                asm("cvt.rna.tf32.f32 %0, %1;" : "=r"(a[mi][3]) : "f"(f3));
            }
            const int br = wn * 32 + (lane >> 2);
            uint32_t bfr[4][2];
#pragma unroll
            for (int nt = 0; nt < 4; nt++) {
                float g0 = Bt[(br + nt * 8) * SST + kc];
                float g1 = Bt[(br + nt * 8) * SST + kc + 4];
                asm("cvt.rna.tf32.f32 %0, %1;" : "=r"(bfr[nt][0]) : "f"(g0));
                asm("cvt.rna.tf32.f32 %0, %1;" : "=r"(bfr[nt][1]) : "f"(g1));
            }
#pragma unroll
            for (int mi = 0; mi < 4; mi++)
#pragma unroll
                for (int nt = 0; nt < 4; nt++) {
                    asm volatile(
                        "mma.sync.aligned.m16n8k8.row.col.f32.tf32.tf32.f32 "
                        "{%0,%1,%2,%3},{%4,%5,%6,%7},{%8,%9},{%0,%1,%2,%3};"
                        : "+f"(acc[mi][nt][0]), "+f"(acc[mi][nt][1]),
                          "+f"(acc[mi][nt][2]), "+f"(acc[mi][nt][3])
                        : "r"(a[mi][0]), "r"(a[mi][1]), "r"(a[mi][2]), "r"(a[mi][3]),
                          "r"(bfr[nt][0]), "r"(bfr[nt][1]));
                }
        }
        __syncthreads();
    }

    const int qr = lane >> 2;
    const int qc = (lane & 3) << 1;
#pragma unroll
    for (int mi = 0; mi < 4; mi++)
#pragma unroll
        for (int nt = 0; nt < 4; nt++) {
            int grow = bm + wm * 64 + mi * 16 + qr;
            int gcol = bn + wn * 32 + nt * 8 + qc;
            float b0 = bias[gcol], b1 = bias[gcol + 1];
            float v0 = acc[mi][nt][0] + b0, v1 = acc[mi][nt][1] + b1;
            float v2 = acc[mi][nt][2] + b0, v3 = acc[mi][nt][3] + b1;
            if (ACT == 1) {
                v0 = fmaxf(v0, 0.f); v1 = fmaxf(v1, 0.f);
                v2 = fmaxf(v2, 0.f); v3 = fmaxf(v3, 0.f);
            } else if (ACT == 2) {
                v0 = 1.f / (1.f + expf(-v0)); v1 = 1.f / (1.f + expf(-v1));
                v2 = 1.f / (1.f + expf(-v2)); v3 = 1.f / (1.f + expf(-v3));
            }
            *reinterpret_cast<float2*>(C + (size_t)grow * N + gcol)       = make_float2(v0, v1);
            *reinterpret_cast<float2*>(C + (size_t)(grow + 8) * N + gcol) = make_float2(v2, v3);
        }
}

// ----------------- attention (L=6, fp32) ------------------------------------
__global__ __launch_bounds__(256) void attn_kernel(
    const float* __restrict__ KV, const float* __restrict__ Q, float* __restrict__ O)
{
    __shared__ __align__(16) float sk[6 * 1024];
    __shared__ __align__(16) float sv[6 * 1024];
    int seq = blockIdx.x;                     // s*2048 + b
    int s = seq >> 11, b = seq & 2047;
    int tid = threadIdx.x;

    const float4* src = reinterpret_cast<const float4*>(KV + (size_t)seq * 12288);
    for (int i = tid; i < 3072; i += 256) {   // 6 tokens x 512 float4
        int tok = i >> 9, c4 = i & 511;
        float4 val = src[i];
        if (c4 < 256) *reinterpret_cast<float4*>(sk + tok * 1024 + c4 * 4) = val;
        else          *reinterpret_cast<float4*>(sv + tok * 1024 + (c4 - 256) * 4) = val;
    }
    __syncthreads();

    int head = tid >> 4, l = tid & 15;
    int dbase = head * 64 + l * 4;            // 16 lanes x 4 elems = hd 64
    int nq = (s == 0) ? 5 : 1;
    for (int iq = 0; iq < nq; iq++) {
        int qrow = (s == 0) ? (b * 5 + iq) : (10240 + b * 5 + (s - 1));
        float4 q = *reinterpret_cast<const float4*>(Q + (size_t)qrow * 1024 + dbase);
        float sc[6];
#pragma unroll
        for (int t = 0; t < 6; t++) {
            const float* kp = sk + t * 1024 + dbase;
            float p = q.x * kp[0] + q.y * kp[1] + q.z * kp[2] + q.w * kp[3];
            p += __shfl_xor_sync(0xffffffffu, p, 1);
            p += __shfl_xor_sync(0xffffffffu, p, 2);
            p += __shfl_xor_sync(0xffffffffu, p, 4);
            p += __shfl_xor_sync(0xffffffffu, p, 8);
            sc[t] = p * 0.125f;               // 1/sqrt(64)
        }
        float mx = sc[0];
#pragma unroll
        for (int t = 1; t < 6; t++) mx = fmaxf(mx, sc[t]);
        float e[6], sum = 0.f;
#pragma unroll
        for (int t = 0; t < 6; t++) { e[t] = expf(sc[t] - mx); sum += e[t]; }
        float inv = 1.f / sum;
        float4 o = make_float4(0.f, 0.f, 0.f, 0.f);
#pragma unroll
        for (int t = 0; t < 6; t++) {
            float w = e[t] * inv;
            const float* vp = sv + t * 1024 + dbase;
            o.x += w * vp[0]; o.y += w * vp[1]; o.z += w * vp[2]; o.w += w * vp[3];
        }
        *reinterpret_cast<float4*>(O + (size_t)qrow * 1024 + dbase) = o;
    }
}

// ----------------- LayerNorm helpers/kernels --------------------------------
__device__ __forceinline__ void stats1024(float s, float q, float& mu, float& rs) {
#pragma unroll
    for (int o = 16; o > 0; o >>= 1) {
        s += __shfl_xor_sync(0xffffffffu, s, o);
        q += __shfl_xor_sync(0xffffffffu, q, o);
    }
    __shared__ float red[18];
    int w = threadIdx.x >> 5, l = threadIdx.x & 31;
    if (l == 0) { red[w] = s; red[8 + w] = q; }
    __syncthreads();
    if (threadIdx.x == 0) {
        float S = 0.f, Qq = 0.f;
#pragma unroll
        for (int i = 0; i < 8; i++) { S += red[i]; Qq += red[8 + i]; }
        float m = S * (1.f / 1024.f);
        red[16] = m;
        red[17] = rsqrtf(Qq * (1.f / 1024.f) - m * m + 1e-5f);
    }
    __syncthreads();
    mu = red[16]; rs = red[17];
}

// rows [0,10240): LN(tgt_noun + aggA, ln1) ; rows [10240,12288): LN(tgt_verb + aggB, ln3)
__global__ __launch_bounds__(256) void ln_pre_kernel(
    const float* __restrict__ feat, const float* __restrict__ aggA, const float* __restrict__ aggB,
    const float* __restrict__ g1, const float* __restrict__ b1,
    const float* __restrict__ g3, const float* __restrict__ b3,
    float* __restrict__ u)
{
    int r = blockIdx.x;
    const float *gp, *bp, *agg;
    size_t foff;
    if (r < 10240) {
        int bb = r / 5, j = r % 5;
        foff = ((size_t)bb * 6 + 1 + j) * 1024;
        agg = aggA + (size_t)bb * 1024; gp = g1; bp = b1;
    } else {
        int bb = r - 10240;
        foff = (size_t)bb * 6144;
        agg = aggB + (size_t)bb * 1024; gp = g3; bp = b3;
    }
    int c = threadIdx.x * 4;
    float4 x = *reinterpret_cast<const float4*>(feat + foff + c);
    float4 a = *reinterpret_cast<const float4*>(agg + c);
    float v[4] = {x.x + a.x, x.y + a.y, x.z + a.z, x.w + a.w};
    float s = 0.f, q = 0.f;
#pragma unroll
    for (int i = 0; i < 4; i++) { s += v[i]; q += v[i] * v[i]; }
    float mu, rs;
    stats1024(s, q, mu, rs);
    float4 y;
    y.x = (v[0] - mu) * rs * gp[c]     + bp[c];
    y.y = (v[1] - mu) * rs * gp[c + 1] + bp[c + 1];
    y.z = (v[2] - mu) * rs * gp[c + 2] + bp[c + 2];
    y.w = (v[3] - mu) * rs * gp[c + 3] + bp[c + 3];
    *reinterpret_cast<float4*>(u + (size_t)r * 1024 + c) = y;
}

// final = LN(u + ffn, ln2/ln4) scattered into output scene 0
__global__ __launch_bounds__(256) void ln_post_kernel(
    const float* __restrict__ u, const float* __restrict__ f,
    const float* __restrict__ g2, const float* __restrict__ b2,
    const float* __restrict__ g4, const float* __restrict__ b4,
    float* __restrict__ out)
{
    int r = blockIdx.x;
    const float *gp, *bp;
    size_t ooff;
    if (r < 10240) {
        int bb = r / 5, j = r % 5;
        ooff = ((size_t)bb * 6 + 1 + j) * 1024;  // final_noun -> tokens 1..5
        gp = g2; bp = b2;
    } else {
        int bb = r - 10240;
        ooff = (size_t)bb * 6144;                // final_verb -> token 0
        gp = g4; bp = b4;
    }
    int c = threadIdx.x * 4;
    size_t off = (size_t)r * 1024 + c;
    float4 xu = *reinterpret_cast<const float4*>(u + off);
    float4 xf = *reinterpret_cast<const float4*>(f + off);
    float v[4] = {xu.x + xf.x, xu.y + xf.y, xu.z + xf.z, xu.w + xf.w};
    float s = 0.f, q = 0.f;
#pragma unroll
    for (int i = 0; i < 4; i++) { s += v[i]; q += v[i] * v[i]; }
    float mu, rs;
    stats1024(s, q, mu, rs);
    float4 y;
    y.x = (v[0] - mu) * rs * gp[c]     + bp[c];
    y.y = (v[1] - mu) * rs * gp[c + 1] + bp[c + 1];
    y.z = (v[2] - mu) * rs * gp[c + 2] + bp[c + 2];
    y.w = (v[3] - mu) * rs * gp[c + 3] + bp[c + 3];
    *reinterpret_cast<float4*>(out + ooff + c) = y;
}

// ----------------- host launcher ---------------------------------------------
extern "C" void kernel_launch(void* const* d_in, const int* in_sizes, int n_in,
                              void* d_out, int out_size)
{
    const float* feat  = (const float*)d_in[0];
    const float* role  = (const float*)d_in[1];
    const float* w_in  = (const float*)d_in[2];
    const float* b_in  = (const float*)d_in[3];
    const float* w_out = (const float*)d_in[4];
    const float* b_out = (const float*)d_in[5];
    const float* ln1g  = (const float*)d_in[6];
    const float* ln1b  = (const float*)d_in[7];
    const float* ln2g  = (const float*)d_in[8];
    const float* ln2b  = (const float*)d_in[9];
    const float* ln3g  = (const float*)d_in[10];
    const float* ln3b  = (const float*)d_in[11];
    const float* ln4g  = (const float*)d_in[12];
    const float* ln4b  = (const float*)d_in[13];
    const float* f1w1  = (const float*)d_in[14];
    const float* f1b1  = (const float*)d_in[15];
    const float* f1w2  = (const float*)d_in[16];
    const float* f1b2  = (const float*)d_in[17];
    const float* f2w1  = (const float*)d_in[18];
    const float* f2b1  = (const float*)d_in[19];
    const float* f2w2  = (const float*)d_in[20];
    const float* f2b2  = (const float*)d_in[21];
    const float* a1w   = (const float*)d_in[22];
    const float* a1b   = (const float*)d_in[23];
    const float* a2w   = (const float*)d_in[24];
    const float* a2b   = (const float*)d_in[25];
    float* out = (float*)d_out;

    const int SMEM = 2 * 2 * 128 * SST * 4;  // 73728 bytes
    cudaFuncSetAttribute(gemm_tf32<0>, cudaFuncAttributeMaxDynamicSharedMemorySize, SMEM);
    cudaFuncSetAttribute(gemm_tf32<1>, cudaFuncAttributeMaxDynamicSharedMemorySize, SMEM);
    cudaFuncSetAttribute(gemm_tf32<2>, cudaFuncAttributeMaxDynamicSharedMemorySize, SMEM);

    float *src, *qsrc, *kv, *q, *o, *m, *hid, *u, *ffn, *aggA, *aggB;
    cudaGetSymbolAddress((void**)&src,  g_src);
    cudaGetSymbolAddress((void**)&qsrc, g_qsrc);
    cudaGetSymbolAddress((void**)&kv,   g_kv);
    cudaGetSymbolAddress((void**)&q,    g_q);
    cudaGetSymbolAddress((void**)&o,    g_o);
    cudaGetSymbolAddress((void**)&m,    g_m);
    cudaGetSymbolAddress((void**)&hid,  g_hid);
    cudaGetSymbolAddress((void**)&u,    g_u);
    cudaGetSymbolAddress((void**)&ffn,  g_ffn);
    cudaGetSymbolAddress((void**)&aggA, g_aggA);
    cudaGetSymbolAddress((void**)&aggB, g_aggB);

    // scenes 1..5 pass through unchanged
    const size_t SCENE = (size_t)2048 * 6 * 1024;  // floats per scene
    cudaMemcpyAsync(out + SCENE, feat + SCENE, 5 * SCENE * sizeof(float),
                    cudaMemcpyDeviceToDevice, 0);

    build_src_kernel<<<73728, 256>>>(feat, role, src, qsrc);

    // K|V projection: [73728,2048] = src @ w_in[1024:3072]^T + b_in[1024:]
    gemm_tf32<0><<<dim3(16, 576), 256, SMEM>>>(src, w_in + 1024 * 1024, b_in + 1024,
                                               kv, 73728, 2048, 1024);
    // Q projection for the 20480 needed queries
    gemm_tf32<0><<<dim3(8, 160), 256, SMEM>>>(qsrc, w_in, b_in, q, 20480, 1024, 1024);

    attn_kernel<<<12288, 256>>>(kv, q, o);

    // out-projection -> messages
    gemm_tf32<0><<<dim3(8, 160), 256, SMEM>>>(o, w_out, b_out, m, 20480, 1024, 1024);

    // agg1: sigmoid(verb msgs [2048,5120] @ agg1_w^T)  -> added to nouns
    gemm_tf32<2><<<dim3(8, 16), 256, SMEM>>>(m + (size_t)10240 * 1024, a1w, a1b,
                                             aggA, 2048, 1024, 5120);
    // agg2: sigmoid(noun msgs [2048,5120] @ agg2_w^T)  -> added to verb
    gemm_tf32<2><<<dim3(8, 16), 256, SMEM>>>(m, a2w, a2b, aggB, 2048, 1024, 5120);

    ln_pre_kernel<<<12288, 256>>>(feat, aggA, aggB, ln1g, ln1b, ln3g, ln3b, u);

    // FFN first GEMM (relu): nouns use ffn1, verb uses ffn2
    gemm_tf32<1><<<dim3(32, 80), 256, SMEM>>>(u, f1w1, f1b1, hid, 10240, 4096, 1024);
    gemm_tf32<1><<<dim3(32, 16), 256, SMEM>>>(u + (size_t)10240 * 1024, f2w1, f2b1,
                                              hid + (size_t)10240 * 4096, 2048, 4096, 1024);
    // FFN second GEMM
    gemm_tf32<0><<<dim3(8, 80), 256, SMEM>>>(hid, f1w2, f1b2, ffn, 10240, 1024, 4096);
    gemm_tf32<0><<<dim3(8, 16), 256, SMEM>>>(hid + (size_t)10240 * 4096, f2w2, f2b2,
                                             ffn + (size_t)10240 * 1024, 2048, 1024, 4096);

    ln_post_kernel<<<12288, 256>>>(u, ffn, ln2g, ln2b, ln4g, ln4b, out);
}

// round 16
// speedup vs baseline: 1.0008x; 1.0008x over previous
#include <cuda_runtime.h>
#include <cuda_bf16.h>
#include <cstdint>
#include <math.h>

// ---------------------------------------------------------------------------
// Problem: D=1024, H=16 (hd=64), DFF=4096, S=5, B=2048, L=6.
// tokens = 6*2048*6 = 73728 ; queries = 20480 ; U rows = 12288
// ---------------------------------------------------------------------------

// ----------------- scratch (device globals; allocation is banned) ----------
__device__ __align__(128) float g_src [75497472];   // [73728,1024] src tokens (verb | noun+role)
__device__ __align__(128) float g_qsrc[20971520];   // [20480,1024] gathered query tokens
__device__ __align__(128) float g_kv  [150994944];  // [73728,2048] K|V
__device__ __align__(128) float g_q   [20971520];   // [20480,1024] Q
__device__ __align__(128) float g_o   [20971520];   // attention out
__device__ __align__(128) float g_m   [20971520];   // messages (after out-proj)
__device__ __align__(128) float g_hid [50331648];   // [12288,4096] ffn hidden
__device__ __align__(128) float g_u   [12582912];   // [12288,1024] post-LN residual input
__device__ __align__(128) float g_ffn [12582912];   // [12288,1024] ffn out
__device__ __align__(128) float g_aggA[2097152];    // sigmoid(verb msgs @ agg1) -> added to nouns
__device__ __align__(128) float g_aggB[2097152];    // sigmoid(noun msgs @ agg2) -> added to verb

// ----------------- build src tokens + gather queries ------------------------
__global__ __launch_bounds__(256) void build_src_kernel(
    const float* __restrict__ feat, const float* __restrict__ role,
    float* __restrict__ src, float* __restrict__ qsrc)
{
    int token = blockIdx.x;                 // ((s*2048+b)*6 + t)
    int t  = token % 6;
    int sb = token / 6;
    int s  = sb >> 11, b = sb & 2047;
    int c  = threadIdx.x * 4;
    float4 v = *reinterpret_cast<const float4*>(feat + (size_t)token * 1024 + c);
    if (t > 0) {
        float4 r = *reinterpret_cast<const float4*>(role + ((size_t)sb * 5 + (t - 1)) * 1024 + c);
        v.x += r.x; v.y += r.y; v.z += r.z; v.w += r.w;
    }
    *reinterpret_cast<float4*>(src + (size_t)token * 1024 + c) = v;
    int qrow = -1;
    if (s == 0 && t > 0)      qrow = b * 5 + (t - 1);          // noun queries (scene 0)
    else if (t == 0 && s > 0) qrow = 10240 + b * 5 + (s - 1);  // verb queries (scenes 1..5)
    if (qrow >= 0)
        *reinterpret_cast<float4*>(qsrc + (size_t)qrow * 1024 + c) = v;
}

// ----------------- generic tf32 GEMM: C = act(A[M,K] @ B[N,K]^T + bias) -----
#define SST 36   // smem row stride (32 + 4 pad) in floats

#define LOAD_TILE(buf, k0)                                                                 \
    {                                                                                      \
        _Pragma("unroll")                                                                  \
        for (int i_ = 0; i_ < 4; i_++) {                                                   \
            int ch = i_ * 256 + tid;                                                       \
            int row = ch >> 3, c4 = ch & 7;                                                \
            const float* pa = Ag + (size_t)(bm + row) * K + (k0) + c4 * 4;                 \
            uint32_t da = sAu + (uint32_t)(((((buf) * 128 + row) * SST) + c4 * 4) * 4);    \
            asm volatile("cp.async.cg.shared.global [%0], [%1], 16;\n" :: "r"(da), "l"(pa)); \
            const float* pb = Bg + (size_t)(bn + row) * K + (k0) + c4 * 4;                 \
            uint32_t db = sBu + (uint32_t)(((((buf) * 128 + row) * SST) + c4 * 4) * 4);    \
            asm volatile("cp.async.cg.shared.global [%0], [%1], 16;\n" :: "r"(db), "l"(pb)); \
        }                                                                                  \
        asm volatile("cp.async.commit_group;\n");                                          \
    }

template <int ACT>  // 0 none, 1 relu, 2 sigmoid
__global__ __launch_bounds__(256) void gemm_tf32(
    const float* __restrict__ Ag, const float* __restrict__ Bg,
    const float* __restrict__ bias, float* __restrict__ C,
    int M, int N, int K)
{
    extern __shared__ float sm[];
    float* sA = sm;                    // [2][128][SST]
    float* sB = sm + 2 * 128 * SST;
    const int tid  = threadIdx.x;
    const int lane = tid & 31, warp = tid >> 5;
    const int wm = warp & 1, wn = warp >> 1;      // 2(M) x 4(N) warps, 64x32 per warp
    const int bm = blockIdx.y * 128, bn = blockIdx.x * 128;
    uint32_t sAu = (uint32_t)__cvta_generic_to_shared(sA);
    uint32_t sBu = (uint32_t)__cvta_generic_to_shared(sB);

    float acc[4][4][4] = {};
    const int KT = K >> 5;

    LOAD_TILE(0, 0);

    for (int kt = 0; kt < KT; kt++) {
        int buf = kt & 1;
        if (kt + 1 < KT) {
            LOAD_TILE(buf ^ 1, (kt + 1) * 32);
            asm volatile("cp.async.wait_group 1;\n");
        } else {
            asm volatile("cp.async.wait_group 0;\n");
        }
        __syncthreads();
        const float* At = sA + buf * 128 * SST;
        const float* Bt = sB + buf * 128 * SST;
#pragma unroll
        for (int ks = 0; ks < 4; ks++) {
            const int kc = ks * 8 + (lane & 3);
            const int ar = wm * 64 + (lane >> 2);
            uint32_t a[4][4];
#pragma unroll
            for (int mi = 0; mi < 4; mi++) {
                float f0 = At[(ar + mi * 16)     * SST + kc];
                float f1 = At[(ar + mi * 16 + 8) * SST + kc];
                float f2 = At[(ar + mi * 16)     * SST + kc + 4];
                float f3 = At[(ar + mi * 16 + 8) * SST + kc + 4];
                asm("cvt.rna.tf32.f32 %0, %1;" : "=r"(a[mi][0]) : "f"(f0));
                asm("cvt.rna.tf32.f32 %0, %1;" : "=r"(a[mi][1]) : "f"(f1));
                asm("cvt.rna.tf32.f32 %0, %1;" : "=r"(a[mi][2]) : "f"(f2));
                asm("cvt.rna.tf32.f32 %0, %1;" : "=r"(a[mi][3]) : "f"(f3));
            }
            const int br = wn * 32 + (lane >> 2);
            uint32_t bfr[4][2];
#pragma unroll
            for (int nt = 0; nt < 4; nt++) {
                float g0 = Bt[(br + nt * 8) * SST + kc];
                float g1 = Bt[(br + nt * 8) * SST + kc + 4];
                asm("cvt.rna.tf32.f32 %0, %1;" : "=r"(bfr[nt][0]) : "f"(g0));
                asm("cvt.rna.tf32.f32 %0, %1;" : "=r"(bfr[nt][1]) : "f"(g1));
            }
#pragma unroll
            for (int mi = 0; mi < 4; mi++)
#pragma unroll
                for (int nt = 0; nt < 4; nt++) {
                    asm volatile(
                        "mma.sync.aligned.m16n8k8.row.col.f32.tf32.tf32.f32 "
                        "{%0,%1,%2,%3},{%4,%5,%6,%7},{%8,%9},{%0,%1,%2,%3};"
                        : "+f"(acc[mi][nt][0]), "+f"(acc[mi][nt][1]),
                          "+f"(acc[mi][nt][2]), "+f"(acc[mi][nt][3])
                        : "r"(a[mi][0]), "r"(a[mi][1]), "r"(a[mi][2]), "r"(a[mi][3]),
                          "r"(bfr[nt][0]), "r"(bfr[nt][1]));
                }
        }
        __syncthreads();
    }

    const int qr = lane >> 2;
    const int qc = (lane & 3) << 1;
#pragma unroll
    for (int mi = 0; mi < 4; mi++)
#pragma unroll
        for (int nt = 0; nt < 4; nt++) {
            int grow = bm + wm * 64 + mi * 16 + qr;
            int gcol = bn + wn * 32 + nt * 8 + qc;
            float b0 = bias[gcol], b1 = bias[gcol + 1];
            float v0 = acc[mi][nt][0] + b0, v1 = acc[mi][nt][1] + b1;
            float v2 = acc[mi][nt][2] + b0, v3 = acc[mi][nt][3] + b1;
            if (ACT == 1) {
                v0 = fmaxf(v0, 0.f); v1 = fmaxf(v1, 0.f);
                v2 = fmaxf(v2, 0.f); v3 = fmaxf(v3, 0.f);
            } else if (ACT == 2) {
                v0 = 1.f / (1.f + expf(-v0)); v1 = 1.f / (1.f + expf(-v1));
                v2 = 1.f / (1.f + expf(-v2)); v3 = 1.f / (1.f + expf(-v3));
            }
            *reinterpret_cast<float2*>(C + (size_t)grow * N + gcol)       = make_float2(v0, v1);
            *reinterpret_cast<float2*>(C + (size_t)(grow + 8) * N + gcol) = make_float2(v2, v3);
        }
}

// ----------------- attention (L=6, fp32) ------------------------------------
__global__ __launch_bounds__(256) void attn_kernel(
    const float* __restrict__ KV, const float* __restrict__ Q, float* __restrict__ O)
{
    __shared__ __align__(16) float sk[6 * 1024];
    __shared__ __align__(16) float sv[6 * 1024];
    int seq = blockIdx.x;                     // s*2048 + b
    int s = seq >> 11, b = seq & 2047;
    int tid = threadIdx.x;

    const float4* src = reinterpret_cast<const float4*>(KV + (size_t)seq * 12288);
    for (int i = tid; i < 3072; i += 256) {   // 6 tokens x 512 float4
        int tok = i >> 9, c4 = i & 511;
        float4 val = src[i];
        if (c4 < 256) *reinterpret_cast<float4*>(sk + tok * 1024 + c4 * 4) = val;
        else          *reinterpret_cast<float4*>(sv + tok * 1024 + (c4 - 256) * 4) = val;
    }
    __syncthreads();

    int head = tid >> 4, l = tid & 15;
    int dbase = head * 64 + l * 4;            // 16 lanes x 4 elems = hd 64
    int nq = (s == 0) ? 5 : 1;
    for (int iq = 0; iq < nq; iq++) {
        int qrow = (s == 0) ? (b * 5 + iq) : (10240 + b * 5 + (s - 1));
        float4 q = *reinterpret_cast<const float4*>(Q + (size_t)qrow * 1024 + dbase);
        float sc[6];
#pragma unroll
        for (int t = 0; t < 6; t++) {
            const float* kp = sk + t * 1024 + dbase;
            float p = q.x * kp[0] + q.y * kp[1] + q.z * kp[2] + q.w * kp[3];
            p += __shfl_xor_sync(0xffffffffu, p, 1);
            p += __shfl_xor_sync(0xffffffffu, p, 2);
            p += __shfl_xor_sync(0xffffffffu, p, 4);
            p += __shfl_xor_sync(0xffffffffu, p, 8);
            sc[t] = p * 0.125f;               // 1/sqrt(64)
        }
        float mx = sc[0];
#pragma unroll
        for (int t = 1; t < 6; t++) mx = fmaxf(mx, sc[t]);
        float e[6], sum = 0.f;
#pragma unroll
        for (int t = 0; t < 6; t++) { e[t] = expf(sc[t] - mx); sum += e[t]; }
        float inv = 1.f / sum;
        float4 o = make_float4(0.f, 0.f, 0.f, 0.f);
#pragma unroll
        for (int t = 0; t < 6; t++) {
            float w = e[t] * inv;
            const float* vp = sv + t * 1024 + dbase;
            o.x += w * vp[0]; o.y += w * vp[1]; o.z += w * vp[2]; o.w += w * vp[3];
        }
        *reinterpret_cast<float4*>(O + (size_t)qrow * 1024 + dbase) = o;
    }
}

// ----------------- LayerNorm helpers/kernels --------------------------------
__device__ __forceinline__ void stats1024(float s, float q, float& mu, float& rs) {
#pragma unroll
    for (int o = 16; o > 0; o >>= 1) {
        s += __shfl_xor_sync(0xffffffffu, s, o);
        q += __shfl_xor_sync(0xffffffffu, q, o);
    }
    __shared__ float red[18];
    int w = threadIdx.x >> 5, l = threadIdx.x & 31;
    if (l == 0) { red[w] = s; red[8 + w] = q; }
    __syncthreads();
    if (threadIdx.x == 0) {
        float S = 0.f, Qq = 0.f;
#pragma unroll
        for (int i = 0; i < 8; i++) { S += red[i]; Qq += red[8 + i]; }
        float m = S * (1.f / 1024.f);
        red[16] = m;
        red[17] = rsqrtf(Qq * (1.f / 1024.f) - m * m + 1e-5f);
    }
    __syncthreads();
    mu = red[16]; rs = red[17];
}

// rows [0,10240): LN(tgt_noun + aggA, ln1) ; rows [10240,12288): LN(tgt_verb + aggB, ln3)
__global__ __launch_bounds__(256) void ln_pre_kernel(
    const float* __restrict__ feat, const float* __restrict__ aggA, const float* __restrict__ aggB,
    const float* __restrict__ g1, const float* __restrict__ b1,
    const float* __restrict__ g3, const float* __restrict__ b3,
    float* __restrict__ u)
{
    int r = blockIdx.x;
    const float *gp, *bp, *agg;
    size_t foff;
    if (r < 10240) {
        int bb = r / 5, j = r % 5;
        foff = ((size_t)bb * 6 + 1 + j) * 1024;
        agg = aggA + (size_t)bb * 1024; gp = g1; bp = b1;
    } else {
        int bb = r - 10240;
        foff = (size_t)bb * 6144;
        agg = aggB + (size_t)bb * 1024; gp = g3; bp = b3;
    }
    int c = threadIdx.x * 4;
    float4 x = *reinterpret_cast<const float4*>(feat + foff + c);
    float4 a = *reinterpret_cast<const float4*>(agg + c);
    float v[4] = {x.x + a.x, x.y + a.y, x.z + a.z, x.w + a.w};
    float s = 0.f, q = 0.f;
#pragma unroll
    for (int i = 0; i < 4; i++) { s += v[i]; q += v[i] * v[i]; }
    float mu, rs;
    stats1024(s, q, mu, rs);
    float4 y;
    y.x = (v[0] - mu) * rs * gp[c]     + bp[c];
    y.y = (v[1] - mu) * rs * gp[c + 1] + bp[c + 1];
    y.z = (v[2] - mu) * rs * gp[c + 2] + bp[c + 2];
    y.w = (v[3] - mu) * rs * gp[c + 3] + bp[c + 3];
    *reinterpret_cast<float4*>(u + (size_t)r * 1024 + c) = y;
}

// final = LN(u + ffn, ln2/ln4) scattered into output scene 0
__global__ __launch_bounds__(256) void ln_post_kernel(
    const float* __restrict__ u, const float* __restrict__ f,
    const float* __restrict__ g2, const float* __restrict__ b2,
    const float* __restrict__ g4, const float* __restrict__ b4,
    float* __restrict__ out)
{
    int r = blockIdx.x;
    const float *gp, *bp;
    size_t ooff;
    if (r < 10240) {
        int bb = r / 5, j = r % 5;
        ooff = ((size_t)bb * 6 + 1 + j) * 1024;  // final_noun -> tokens 1..5
        gp = g2; bp = b2;
    } else {
        int bb = r - 10240;
        ooff = (size_t)bb * 6144;                // final_verb -> token 0
        gp = g4; bp = b4;
    }
    int c = threadIdx.x * 4;
    size_t off = (size_t)r * 1024 + c;
    float4 xu = *reinterpret_cast<const float4*>(u + off);
    float4 xf = *reinterpret_cast<const float4*>(f + off);
    float v[4] = {xu.x + xf.x, xu.y + xf.y, xu.z + xf.z, xu.w + xf.w};
    float s = 0.f, q = 0.f;
#pragma unroll
    for (int i = 0; i < 4; i++) { s += v[i]; q += v[i] * v[i]; }
    float mu, rs;
    stats1024(s, q, mu, rs);
    float4 y;
    y.x = (v[0] - mu) * rs * gp[c]     + bp[c];
    y.y = (v[1] - mu) * rs * gp[c + 1] + bp[c + 1];
    y.z = (v[2] - mu) * rs * gp[c + 2] + bp[c + 2];
    y.w = (v[3] - mu) * rs * gp[c + 3] + bp[c + 3];
    *reinterpret_cast<float4*>(out + ooff + c) = y;
}

// ----------------- host launcher ---------------------------------------------
extern "C" void kernel_launch(void* const* d_in, const int* in_sizes, int n_in,
                              void* d_out, int out_size)
{
    const float* feat  = (const float*)d_in[0];
    const float* role  = (const float*)d_in[1];
    const float* w_in  = (const float*)d_in[2];
    const float* b_in  = (const float*)d_in[3];
    const float* w_out = (const float*)d_in[4];
    const float* b_out = (const float*)d_in[5];
    const float* ln1g  = (const float*)d_in[6];
    const float* ln1b  = (const float*)d_in[7];
    const float* ln2g  = (const float*)d_in[8];
    const float* ln2b  = (const float*)d_in[9];
    const float* ln3g  = (const float*)d_in[10];
    const float* ln3b  = (const float*)d_in[11];
    const float* ln4g  = (const float*)d_in[12];
    const float* ln4b  = (const float*)d_in[13];
    const float* f1w1  = (const float*)d_in[14];
    const float* f1b1  = (const float*)d_in[15];
    const float* f1w2  = (const float*)d_in[16];
    const float* f1b2  = (const float*)d_in[17];
    const float* f2w1  = (const float*)d_in[18];
    const float* f2b1  = (const float*)d_in[19];
    const float* f2w2  = (const float*)d_in[20];
    const float* f2b2  = (const float*)d_in[21];
    const float* a1w   = (const float*)d_in[22];
    const float* a1b   = (const float*)d_in[23];
    const float* a2w   = (const float*)d_in[24];
    const float* a2b   = (const float*)d_in[25];
    float* out = (float*)d_out;

    const int SMEM = 2 * 2 * 128 * SST * 4;  // 73728 bytes
    cudaFuncSetAttribute(gemm_tf32<0>, cudaFuncAttributeMaxDynamicSharedMemorySize, SMEM);
    cudaFuncSetAttribute(gemm_tf32<1>, cudaFuncAttributeMaxDynamicSharedMemorySize, SMEM);
    cudaFuncSetAttribute(gemm_tf32<2>, cudaFuncAttributeMaxDynamicSharedMemorySize, SMEM);

    float *src, *qsrc, *kv, *q, *o, *m, *hid, *u, *ffn, *aggA, *aggB;
    cudaGetSymbolAddress((void**)&src,  g_src);
    cudaGetSymbolAddress((void**)&qsrc, g_qsrc);
    cudaGetSymbolAddress((void**)&kv,   g_kv);
    cudaGetSymbolAddress((void**)&q,    g_q);
    cudaGetSymbolAddress((void**)&o,    g_o);
    cudaGetSymbolAddress((void**)&m,    g_m);
    cudaGetSymbolAddress((void**)&hid,  g_hid);
    cudaGetSymbolAddress((void**)&u,    g_u);
    cudaGetSymbolAddress((void**)&ffn,  g_ffn);
    cudaGetSymbolAddress((void**)&aggA, g_aggA);
    cudaGetSymbolAddress((void**)&aggB, g_aggB);

    // scenes 1..5 pass through unchanged
    const size_t SCENE = (size_t)2048 * 6 * 1024;  // floats per scene
    cudaMemcpyAsync(out + SCENE, feat + SCENE, 5 * SCENE * sizeof(float),
                    cudaMemcpyDeviceToDevice, 0);

    build_src_kernel<<<73728, 256>>>(feat, role, src, qsrc);

    // K|V projection: [73728,2048] = src @ w_in[1024:3072]^T + b_in[1024:]
    gemm_tf32<0><<<dim3(16, 576), 256, SMEM>>>(src, w_in + 1024 * 1024, b_in + 1024,
                                               kv, 73728, 2048, 1024);
    // Q projection for the 20480 needed queries
    gemm_tf32<0><<<dim3(8, 160), 256, SMEM>>>(qsrc, w_in, b_in, q, 20480, 1024, 1024);

    attn_kernel<<<12288, 256>>>(kv, q, o);

    // out-projection -> messages
    gemm_tf32<0><<<dim3(8, 160), 256, SMEM>>>(o, w_out, b_out, m, 20480, 1024, 1024);

    // agg1: sigmoid(verb msgs [2048,5120] @ agg1_w^T)  -> added to nouns
    gemm_tf32<2><<<dim3(8, 16), 256, SMEM>>>(m + (size_t)10240 * 1024, a1w, a1b,
                                             aggA, 2048, 1024, 5120);
    // agg2: sigmoid(noun msgs [2048,5120] @ agg2_w^T)  -> added to verb
    gemm_tf32<2><<<dim3(8, 16), 256, SMEM>>>(m, a2w, a2b, aggB, 2048, 1024, 5120);

    ln_pre_kernel<<<12288, 256>>>(feat, aggA, aggB, ln1g, ln1b, ln3g, ln3b, u);

    // FFN first GEMM (relu): nouns use ffn1, verb uses ffn2
    gemm_tf32<1><<<dim3(32, 80), 256, SMEM>>>(u, f1w1, f1b1, hid, 10240, 4096, 1024);
    gemm_tf32<1><<<dim3(32, 16), 256, SMEM>>>(u + (size_t)10240 * 1024, f2w1, f2b1,
                                              hid + (size_t)10240 * 4096, 2048, 4096, 1024);
    // FFN second GEMM
    gemm_tf32<0><<<dim3(8, 80), 256, SMEM>>>(hid, f1w2, f1b2, ffn, 10240, 1024, 4096);
    gemm_tf32<0><<<dim3(8, 16), 256, SMEM>>>(hid + (size_t)10240 * 4096, f2w2, f2b2,
                                             ffn + (size_t)10240 * 1024, 2048, 1024, 4096);

    ln_post_kernel<<<12288, 256>>>(u, ffn, ln2g, ln2b, ln4g, ln4b, out);
}

// round 17
// speedup vs baseline: 2.1110x; 2.1093x over previous
#include <cuda_runtime.h>
#include <cuda_fp16.h>
#include <cstdint>
#include <math.h>

// ---------------------------------------------------------------------------
// D=1024, H=16 (hd=64), DFF=4096, S=5, B=2048, L=6
// tokens = 73728 ; queries = 20480 ; U rows = 12288
// ---------------------------------------------------------------------------

// ----------------- scratch (device globals; allocation banned) -------------
__device__ __align__(128) unsigned short g_src [75497472];   // [73728,1024] h
__device__ __align__(128) unsigned short g_qsrc[20971520];   // [20480,1024] h
__device__ __align__(128) unsigned short g_kv  [150994944];  // [73728,2048] h
__device__ __align__(128) unsigned short g_q   [20971520];   // h
__device__ __align__(128) unsigned short g_o   [20971520];   // h
__device__ __align__(128) unsigned short g_m   [20971520];   // h
__device__ __align__(128) unsigned short g_hid [50331648];   // [12288,4096] h
__device__ __align__(128) unsigned short g_u16 [12582912];   // post-LN half
__device__ __align__(128) unsigned short g_wh  [31457280];   // all weights half
__device__ __align__(128) float g_u32 [12582912];            // post-LN fp32
__device__ __align__(128) float g_ffn [12582912];            // ffn out fp32
__device__ __align__(128) float g_aggA[2097152];
__device__ __align__(128) float g_aggB[2097152];

// ----------------- fp32 -> fp16 convert -------------------------------------
__global__ __launch_bounds__(256) void f2h_kernel(const float* __restrict__ s,
                                                  __half* __restrict__ d, int n4) {
    int i = blockIdx.x * 256 + threadIdx.x;
    int stride = gridDim.x * 256;
    for (; i < n4; i += stride) {
        float4 v = reinterpret_cast<const float4*>(s)[i];
        __half2 p0 = __floats2half2_rn(v.x, v.y);
        __half2 p1 = __floats2half2_rn(v.z, v.w);
        reinterpret_cast<__half2*>(d)[2 * i]     = p0;
        reinterpret_cast<__half2*>(d)[2 * i + 1] = p1;
    }
}

// ----------------- build src tokens (half) + gather queries -----------------
__global__ __launch_bounds__(256) void build_src_kernel(
    const float* __restrict__ feat, const float* __restrict__ role,
    __half* __restrict__ src, __half* __restrict__ qsrc)
{
    int token = blockIdx.x;                 // ((s*2048+b)*6 + t)
    int t  = token % 6;
    int sb = token / 6;
    int s  = sb >> 11, b = sb & 2047;
    int c  = threadIdx.x * 4;
    float4 v = *reinterpret_cast<const float4*>(feat + (size_t)token * 1024 + c);
    if (t > 0) {
        float4 r = *reinterpret_cast<const float4*>(role + ((size_t)sb * 5 + (t - 1)) * 1024 + c);
        v.x += r.x; v.y += r.y; v.z += r.z; v.w += r.w;
    }
    __half2 p0 = __floats2half2_rn(v.x, v.y);
    __half2 p1 = __floats2half2_rn(v.z, v.w);
    __half* dp = src + (size_t)token * 1024 + c;
    *reinterpret_cast<__half2*>(dp)     = p0;
    *reinterpret_cast<__half2*>(dp + 2) = p1;
    int qrow = -1;
    if (s == 0 && t > 0)      qrow = b * 5 + (t - 1);          // noun queries (scene 0)
    else if (t == 0 && s > 0) qrow = 10240 + b * 5 + (s - 1);  // verb queries (scenes 1..5)
    if (qrow >= 0) {
        __half* qp = qsrc + (size_t)qrow * 1024 + c;
        *reinterpret_cast<__half2*>(qp)     = p0;
        *reinterpret_cast<__half2*>(qp + 2) = p1;
    }
}

// ----------------- fp16 GEMM: C = act(A[M,K] @ B[N,K]^T + bias) -------------
// 128x128 block, K-tile 64, double-buffered cp.async, ldmatrix + m16n8k16.
#define SSTH 72   // smem row stride in halves (64 + 8 pad -> 144B, conflict-free)

#define LOAD_TILE(buf, k0)                                                                   \
    {                                                                                        \
        _Pragma("unroll")                                                                    \
        for (int i_ = 0; i_ < 4; i_++) {                                                     \
            int ch = i_ * 256 + tid;                                                         \
            int row = ch >> 3, c8 = ch & 7;                                                  \
            const __half* pa = Ag + (size_t)(bm + row) * K + (k0) + c8 * 8;                  \
            uint32_t da = sAu + (uint32_t)((((buf) * 128 + row) * SSTH + c8 * 8) * 2);       \
            asm volatile("cp.async.cg.shared.global [%0], [%1], 16;\n" :: "r"(da), "l"(pa)); \
            const __half* pb = Bg + (size_t)(bn + row) * K + (k0) + c8 * 8;                  \
            uint32_t db = sBu + (uint32_t)((((buf) * 128 + row) * SSTH + c8 * 8) * 2);       \
            asm volatile("cp.async.cg.shared.global [%0], [%1], 16;\n" :: "r"(db), "l"(pb)); \
        }                                                                                    \
        asm volatile("cp.async.commit_group;\n");                                            \
    }

__device__ __forceinline__ void store2(float* C, size_t idx, float v0, float v1) {
    *reinterpret_cast<float2*>(C + idx) = make_float2(v0, v1);
}
__device__ __forceinline__ void store2(__half* C, size_t idx, float v0, float v1) {
    *reinterpret_cast<__half2*>(C + idx) = __floats2half2_rn(v0, v1);
}

template <int ACT, typename OutT>  // ACT: 0 none, 1 relu, 2 sigmoid
__global__ __launch_bounds__(256) void gemm_h(
    const __half* __restrict__ Ag, const __half* __restrict__ Bg,
    const float* __restrict__ bias, OutT* __restrict__ C,
    int M, int N, int K)
{
    extern __shared__ __half sm[];
    const int tid  = threadIdx.x;
    const int lane = tid & 31, warp = tid >> 5;
    const int wm = warp & 1, wn = warp >> 1;        // 2(M) x 4(N) warps: 64x32 each
    const int bm = blockIdx.y * 128, bn = blockIdx.x * 128;
    uint32_t sAu = (uint32_t)__cvta_generic_to_shared(sm);
    uint32_t sBu = sAu + 2 * 128 * SSTH * 2;

    float acc[4][4][4] = {};
    const int KT = K >> 6;

    LOAD_TILE(0, 0);

    const int lm_arow = (lane & 15);            // A: row within 16
    const int lm_acol = (lane >> 4) << 3;       // A: col 0 or 8
    const int g  = lane >> 3;                   // B matrix select
    const int r8 = lane & 7;

    for (int kt = 0; kt < KT; kt++) {
        int buf = kt & 1;
        if (kt + 1 < KT) {
            LOAD_TILE(buf ^ 1, (kt + 1) * 64);
            asm volatile("cp.async.wait_group 1;\n");
        } else {
            asm volatile("cp.async.wait_group 0;\n");
        }
        __syncthreads();
        uint32_t baseA = sAu + (uint32_t)(buf * 128 * SSTH * 2);
        uint32_t baseB = sBu + (uint32_t)(buf * 128 * SSTH * 2);
#pragma unroll
        for (int ks = 0; ks < 4; ks++) {
            uint32_t a[4][4], bb[4][2];
#pragma unroll
            for (int mi = 0; mi < 4; mi++) {
                int row = wm * 64 + mi * 16 + lm_arow;
                int col = ks * 16 + lm_acol;
                uint32_t ad = baseA + (uint32_t)((row * SSTH + col) * 2);
                asm volatile("ldmatrix.sync.aligned.m8n8.x4.shared.b16 {%0,%1,%2,%3}, [%4];"
                             : "=r"(a[mi][0]), "=r"(a[mi][1]), "=r"(a[mi][2]), "=r"(a[mi][3])
                             : "r"(ad));
            }
#pragma unroll
            for (int nh = 0; nh < 2; nh++) {
                int nblk = nh * 2 + (g >> 1);
                int kblk = g & 1;
                int row = wn * 32 + nblk * 8 + r8;
                int col = ks * 16 + kblk * 8;
                uint32_t ad = baseB + (uint32_t)((row * SSTH + col) * 2);
                asm volatile("ldmatrix.sync.aligned.m8n8.x4.shared.b16 {%0,%1,%2,%3}, [%4];"
                             : "=r"(bb[2 * nh][0]), "=r"(bb[2 * nh][1]),
                               "=r"(bb[2 * nh + 1][0]), "=r"(bb[2 * nh + 1][1])
                             : "r"(ad));
            }
#pragma unroll
            for (int mi = 0; mi < 4; mi++)
#pragma unroll
                for (int nt = 0; nt < 4; nt++) {
                    asm volatile(
                        "mma.sync.aligned.m16n8k16.row.col.f32.f16.f16.f32 "
                        "{%0,%1,%2,%3},{%4,%5,%6,%7},{%8,%9},{%0,%1,%2,%3};"
                        : "+f"(acc[mi][nt][0]), "+f"(acc[mi][nt][1]),
                          "+f"(acc[mi][nt][2]), "+f"(acc[mi][nt][3])
                        : "r"(a[mi][0]), "r"(a[mi][1]), "r"(a[mi][2]), "r"(a[mi][3]),
                          "r"(bb[nt][0]), "r"(bb[nt][1]));
                }
        }
        __syncthreads();
    }

    const int qr = lane >> 2;
    const int qc = (lane & 3) << 1;
#pragma unroll
    for (int mi = 0; mi < 4; mi++)
#pragma unroll
        for (int nt = 0; nt < 4; nt++) {
            int grow = bm + wm * 64 + mi * 16 + qr;
            int gcol = bn + wn * 32 + nt * 8 + qc;
            float b0 = bias[gcol], b1 = bias[gcol + 1];
            float v0 = acc[mi][nt][0] + b0, v1 = acc[mi][nt][1] + b1;
            float v2 = acc[mi][nt][2] + b0, v3 = acc[mi][nt][3] + b1;
            if (ACT == 1) {
                v0 = fmaxf(v0, 0.f); v1 = fmaxf(v1, 0.f);
                v2 = fmaxf(v2, 0.f); v3 = fmaxf(v3, 0.f);
            } else if (ACT == 2) {
                v0 = 1.f / (1.f + expf(-v0)); v1 = 1.f / (1.f + expf(-v1));
                v2 = 1.f / (1.f + expf(-v2)); v3 = 1.f / (1.f + expf(-v3));
            }
            store2(C, (size_t)grow * N + gcol, v0, v1);
            store2(C, (size_t)(grow + 8) * N + gcol, v2, v3);
        }
}

// ----------------- attention (L=6, fp32 math over half K/V/Q) ---------------
__global__ __launch_bounds__(256) void attn_kernel(
    const __half* __restrict__ KV, const __half* __restrict__ Q, __half* __restrict__ O)
{
    __shared__ __align__(16) __half sk[6 * 1024];
    __shared__ __align__(16) __half sv[6 * 1024];
    int seq = blockIdx.x;                     // s*2048 + b
    int s = seq >> 11, b = seq & 2047;
    int tid = threadIdx.x;

    const uint4* src = reinterpret_cast<const uint4*>(KV + (size_t)seq * 12288);
    for (int i = tid; i < 1536; i += 256) {   // 6 tokens x 256 uint4 (8 halves each)
        int tok = i >> 8, c8 = i & 255;
        uint4 val = src[i];
        if (c8 < 128) *reinterpret_cast<uint4*>(sk + tok * 1024 + c8 * 8) = val;
        else          *reinterpret_cast<uint4*>(sv + tok * 1024 + (c8 - 128) * 8) = val;
    }
    __syncthreads();

    int head = tid >> 4, l = tid & 15;
    int dbase = head * 64 + l * 4;            // 16 lanes x 4 elems = hd 64
    int nq = (s == 0) ? 5 : 1;
    for (int iq = 0; iq < nq; iq++) {
        int qrow = (s == 0) ? (b * 5 + iq) : (10240 + b * 5 + (s - 1));
        const __half2* qp = reinterpret_cast<const __half2*>(Q + (size_t)qrow * 1024 + dbase);
        float2 qa = __half22float2(qp[0]);
        float2 qb = __half22float2(qp[1]);
        float sc[6];
#pragma unroll
        for (int t = 0; t < 6; t++) {
            const __half2* kp = reinterpret_cast<const __half2*>(sk + t * 1024 + dbase);
            float2 k0 = __half22float2(kp[0]);
            float2 k1 = __half22float2(kp[1]);
            float p = qa.x * k0.x + qa.y * k0.y + qb.x * k1.x + qb.y * k1.y;
            p += __shfl_xor_sync(0xffffffffu, p, 1);
            p += __shfl_xor_sync(0xffffffffu, p, 2);
            p += __shfl_xor_sync(0xffffffffu, p, 4);
            p += __shfl_xor_sync(0xffffffffu, p, 8);
            sc[t] = p * 0.125f;               // 1/sqrt(64)
        }
        float mx = sc[0];
#pragma unroll
        for (int t = 1; t < 6; t++) mx = fmaxf(mx, sc[t]);
        float e[6], sum = 0.f;
#pragma unroll
        for (int t = 0; t < 6; t++) { e[t] = expf(sc[t] - mx); sum += e[t]; }
        float inv = 1.f / sum;
        float o0 = 0.f, o1 = 0.f, o2 = 0.f, o3 = 0.f;
#pragma unroll
        for (int t = 0; t < 6; t++) {
            float w = e[t] * inv;
            const __half2* vp = reinterpret_cast<const __half2*>(sv + t * 1024 + dbase);
            float2 v0 = __half22float2(vp[0]);
            float2 v1 = __half22float2(vp[1]);
            o0 += w * v0.x; o1 += w * v0.y; o2 += w * v1.x; o3 += w * v1.y;
        }
        __half* op = O + (size_t)qrow * 1024 + dbase;
        *reinterpret_cast<__half2*>(op)     = __floats2half2_rn(o0, o1);
        *reinterpret_cast<__half2*>(op + 2) = __floats2half2_rn(o2, o3);
    }
}

// ----------------- LayerNorm helpers/kernels --------------------------------
__device__ __forceinline__ void stats1024(float s, float q, float& mu, float& rs) {
#pragma unroll
    for (int o = 16; o > 0; o >>= 1) {
        s += __shfl_xor_sync(0xffffffffu, s, o);
        q += __shfl_xor_sync(0xffffffffu, q, o);
    }
    __shared__ float red[18];
    int w = threadIdx.x >> 5, l = threadIdx.x & 31;
    if (l == 0) { red[w] = s; red[8 + w] = q; }
    __syncthreads();
    if (threadIdx.x == 0) {
        float S = 0.f, Qq = 0.f;
#pragma unroll
        for (int i = 0; i < 8; i++) { S += red[i]; Qq += red[8 + i]; }
        float m = S * (1.f / 1024.f);
        red[16] = m;
        red[17] = rsqrtf(Qq * (1.f / 1024.f) - m * m + 1e-5f);
    }
    __syncthreads();
    mu = red[16]; rs = red[17];
}

// rows [0,10240): LN(tgt_noun + aggA, ln1) ; rows [10240,12288): LN(tgt_verb + aggB, ln3)
__global__ __launch_bounds__(256) void ln_pre_kernel(
    const float* __restrict__ feat, const float* __restrict__ aggA, const float* __restrict__ aggB,
    const float* __restrict__ g1, const float* __restrict__ b1,
    const float* __restrict__ g3, const float* __restrict__ b3,
    float* __restrict__ u32, __half* __restrict__ u16)
{
    int r = blockIdx.x;
    const float *gp, *bp, *agg;
    size_t foff;
    if (r < 10240) {
        int bb = r / 5, j = r % 5;
        foff = ((size_t)bb * 6 + 1 + j) * 1024;
        agg = aggA + (size_t)bb * 1024; gp = g1; bp = b1;
    } else {
        int bb = r - 10240;
        foff = (size_t)bb * 6144;
        agg = aggB + (size_t)bb * 1024; gp = g3; bp = b3;
    }
    int c = threadIdx.x * 4;
    float4 x = *reinterpret_cast<const float4*>(feat + foff + c);
    float4 a = *reinterpret_cast<const float4*>(agg + c);
    float v[4] = {x.x + a.x, x.y + a.y, x.z + a.z, x.w + a.w};
    float s = 0.f, q = 0.f;
#pragma unroll
    for (int i = 0; i < 4; i++) { s += v[i]; q += v[i] * v[i]; }
    float mu, rs;
    stats1024(s, q, mu, rs);
    float y0 = (v[0] - mu) * rs * gp[c]     + bp[c];
    float y1 = (v[1] - mu) * rs * gp[c + 1] + bp[c + 1];
    float y2 = (v[2] - mu) * rs * gp[c + 2] + bp[c + 2];
    float y3 = (v[3] - mu) * rs * gp[c + 3] + bp[c + 3];
    size_t off = (size_t)r * 1024 + c;
    *reinterpret_cast<float4*>(u32 + off) = make_float4(y0, y1, y2, y3);
    *reinterpret_cast<__half2*>(u16 + off)     = __floats2half2_rn(y0, y1);
    *reinterpret_cast<__half2*>(u16 + off + 2) = __floats2half2_rn(y2, y3);
}

// final = LN(u + ffn, ln2/ln4) scattered into output scene 0
__global__ __launch_bounds__(256) void ln_post_kernel(
    const float* __restrict__ u, const float* __restrict__ f,
    const float* __restrict__ g2, const float* __restrict__ b2,
    const float* __restrict__ g4, const float* __restrict__ b4,
    float* __restrict__ out)
{
    int r = blockIdx.x;
    const float *gp, *bp;
    size_t ooff;
    if (r < 10240) {
        int bb = r / 5, j = r % 5;
        ooff = ((size_t)bb * 6 + 1 + j) * 1024;  // final_noun -> tokens 1..5
        gp = g2; bp = b2;
    } else {
        int bb = r - 10240;
        ooff = (size_t)bb * 6144;                // final_verb -> token 0
        gp = g4; bp = b4;
    }
    int c = threadIdx.x * 4;
    size_t off = (size_t)r * 1024 + c;
    float4 xu = *reinterpret_cast<const float4*>(u + off);
    float4 xf = *reinterpret_cast<const float4*>(f + off);
    float v[4] = {xu.x + xf.x, xu.y + xf.y, xu.z + xf.z, xu.w + xf.w};
    float s = 0.f, q = 0.f;
#pragma unroll
    for (int i = 0; i < 4; i++) { s += v[i]; q += v[i] * v[i]; }
    float mu, rs;
    stats1024(s, q, mu, rs);
    float4 y;
    y.x = (v[0] - mu) * rs * gp[c]     + bp[c];
    y.y = (v[1] - mu) * rs * gp[c + 1] + bp[c + 1];
    y.z = (v[2] - mu) * rs * gp[c + 2] + bp[c + 2];
    y.w = (v[3] - mu) * rs * gp[c + 3] + bp[c + 3];
    *reinterpret_cast<float4*>(out + ooff + c) = y;
}

// ----------------- host launcher ---------------------------------------------
extern "C" void kernel_launch(void* const* d_in, const int* in_sizes, int n_in,
                              void* d_out, int out_size)
{
    const float* feat  = (const float*)d_in[0];
    const float* role  = (const float*)d_in[1];
    const float* w_in  = (const float*)d_in[2];
    const float* b_in  = (const float*)d_in[3];
    const float* w_out = (const float*)d_in[4];
    const float* b_out = (const float*)d_in[5];
    const float* ln1g  = (const float*)d_in[6];
    const float* ln1b  = (const float*)d_in[7];
    const float* ln2g  = (const float*)d_in[8];
    const float* ln2b  = (const float*)d_in[9];
    const float* ln3g  = (const float*)d_in[10];
    const float* ln3b  = (const float*)d_in[11];
    const float* ln4g  = (const float*)d_in[12];
    const float* ln4b  = (const float*)d_in[13];
    const float* f1w1  = (const float*)d_in[14];
    const float* f1b1  = (const float*)d_in[15];
    const float* f1w2  = (const float*)d_in[16];
    const float* f1b2  = (const float*)d_in[17];
    const float* f2w1  = (const float*)d_in[18];
    const float* f2b1  = (const float*)d_in[19];
    const float* f2w2  = (const float*)d_in[20];
    const float* f2b2  = (const float*)d_in[21];
    const float* a1w   = (const float*)d_in[22];
    const float* a1b   = (const float*)d_in[23];
    const float* a2w   = (const float*)d_in[24];
    const float* a2b   = (const float*)d_in[25];
    float* out = (float*)d_out;

    const int SMEM = 2 * 2 * 128 * SSTH * 2;  // 73728 bytes
    cudaFuncSetAttribute(gemm_h<0, __half>, cudaFuncAttributeMaxDynamicSharedMemorySize, SMEM);
    cudaFuncSetAttribute(gemm_h<1, __half>, cudaFuncAttributeMaxDynamicSharedMemorySize, SMEM);
    cudaFuncSetAttribute(gemm_h<0, float>,  cudaFuncAttributeMaxDynamicSharedMemorySize, SMEM);
    cudaFuncSetAttribute(gemm_h<2, float>,  cudaFuncAttributeMaxDynamicSharedMemorySize, SMEM);

    __half *src, *qsrc, *kv, *q, *o, *m, *hid, *u16, *wh;
    float *u32, *ffn, *aggA, *aggB;
    cudaGetSymbolAddress((void**)&src,  g_src);
    cudaGetSymbolAddress((void**)&qsrc, g_qsrc);
    cudaGetSymbolAddress((void**)&kv,   g_kv);
    cudaGetSymbolAddress((void**)&q,    g_q);
    cudaGetSymbolAddress((void**)&o,    g_o);
    cudaGetSymbolAddress((void**)&m,    g_m);
    cudaGetSymbolAddress((void**)&hid,  g_hid);
    cudaGetSymbolAddress((void**)&u16,  g_u16);
    cudaGetSymbolAddress((void**)&wh,   g_wh);
    cudaGetSymbolAddress((void**)&u32,  g_u32);
    cudaGetSymbolAddress((void**)&ffn,  g_ffn);
    cudaGetSymbolAddress((void**)&aggA, g_aggA);
    cudaGetSymbolAddress((void**)&aggB, g_aggB);

    // half weight slots inside g_wh
    __half* winh  = wh;
    __half* wouth = wh + 3145728;
    __half* f1w1h = wh + 4194304;
    __half* f1w2h = wh + 8388608;
    __half* f2w1h = wh + 12582912;
    __half* f2w2h = wh + 16777216;
    __half* a1wh  = wh + 20971520;
    __half* a2wh  = wh + 26214400;

    // scenes 1..5 pass through unchanged
    const size_t SCENE = (size_t)2048 * 6 * 1024;  // floats per scene
    cudaMemcpyAsync(out + SCENE, feat + SCENE, 5 * SCENE * sizeof(float),
                    cudaMemcpyDeviceToDevice, 0);

    // weight conversions (fp32 -> fp16)
    f2h_kernel<<<1024, 256>>>(w_in,  winh,  3145728 / 4);
    f2h_kernel<<<512,  256>>>(w_out, wouth, 1048576 / 4);
    f2h_kernel<<<1024, 256>>>(f1w1,  f1w1h, 4194304 / 4);
    f2h_kernel<<<1024, 256>>>(f1w2,  f1w2h, 4194304 / 4);
    f2h_kernel<<<1024, 256>>>(f2w1,  f2w1h, 4194304 / 4);
    f2h_kernel<<<1024, 256>>>(f2w2,  f2w2h, 4194304 / 4);
    f2h_kernel<<<1024, 256>>>(a1w,   a1wh,  5242880 / 4);
    f2h_kernel<<<1024, 256>>>(a2w,   a2wh,  5242880 / 4);

    build_src_kernel<<<73728, 256>>>(feat, role, src, qsrc);

    // K|V projection: [73728,2048] = src @ w_in[1024:3072]^T + b_in[1024:]
    gemm_h<0, __half><<<dim3(16, 576), 256, SMEM>>>(src, winh + (size_t)1024 * 1024,
                                                    b_in + 1024, kv, 73728, 2048, 1024);
    // Q projection for the 20480 needed queries
    gemm_h<0, __half><<<dim3(8, 160), 256, SMEM>>>(qsrc, winh, b_in, q, 20480, 1024, 1024);

    attn_kernel<<<12288, 256>>>(kv, q, o);

    // out-projection -> messages
    gemm_h<0, __half><<<dim3(8, 160), 256, SMEM>>>(o, wouth, b_out, m, 20480, 1024, 1024);

    // agg1: sigmoid(verb msgs [2048,5120] @ agg1_w^T) -> added to nouns
    gemm_h<2, float><<<dim3(8, 16), 256, SMEM>>>(m + (size_t)10240 * 1024, a1wh, a1b,
                                                 aggA, 2048, 1024, 5120);
    // agg2: sigmoid(noun msgs [2048,5120] @ agg2_w^T) -> added to verb
    gemm_h<2, float><<<dim3(8, 16), 256, SMEM>>>(m, a2wh, a2b, aggB, 2048, 1024, 5120);

    ln_pre_kernel<<<12288, 256>>>(feat, aggA, aggB, ln1g, ln1b, ln3g, ln3b, u32, u16);

    // FFN first GEMM (relu): nouns use ffn1, verb uses ffn2
    gemm_h<1, __half><<<dim3(32, 80), 256, SMEM>>>(u16, f1w1h, f1b1, hid, 10240, 4096, 1024);
    gemm_h<1, __half><<<dim3(32, 16), 256, SMEM>>>(u16 + (size_t)10240 * 1024, f2w1h, f2b1,
                                                   hid + (size_t)10240 * 4096, 2048, 4096, 1024);
    // FFN second GEMM
    gemm_h<0, float><<<dim3(8, 80), 256, SMEM>>>(hid, f1w2h, f1b2, ffn, 10240, 1024, 4096);
    gemm_h<0, float><<<dim3(8, 16), 256, SMEM>>>(hid + (size_t)10240 * 4096, f2w2h, f2b2,
                                                 ffn + (size_t)10240 * 1024, 2048, 1024, 4096);

    ln_post_kernel<<<12288, 256>>>(u32, ffn, ln2g, ln2b, ln4g, ln4b, out);
}